// round 9
// baseline (speedup 1.0000x reference)
#include <cuda_runtime.h>
#include <cuda_bf16.h>

// Problem constants: b=1, h=w=64, s=5, H=W=1024, ps=32, q=8
#define GRID_T   64
#define NTILES   (GRID_T * GRID_T)      // 4096
#define NSTROKE  5
#define IMG      1024
#define PLANE    (IMG * IMG)            // 1048576
#define NCELL    65                     // padded cells per axis
#define TOTCELL  (NCELL * NCELL)        // 4225

// Scratch (allocation-free rule: __device__ globals)
__device__ int    g_cnt[NTILES];
__device__ float4 g_sA[NTILES * NSTROKE];   // (C, S, U0, V0)   [scaled by 25]
__device__ float4 g_sB[NTILES * NSTROKE];   // (W, H, -, -)     [scaled by 25]
__device__ float4 g_sC[NTILES * NSTROKE];   // (cr, cg, cb, -)

__device__ __forceinline__ float tanh_(float x) {
    float r; asm("tanh.approx.f32 %0,%1;" : "=f"(r) : "f"(x)); return r;
}

// ---------------------------------------------------------------------------
// Kernel 1: per-STROKE preprocessing, order-preserving compaction of dec==1.
// sigmoid(50*(hw-|u|)) = 0.5*(1+tanh(25*(hw-|u|))) -> fold 25 into coeffs.
// ---------------------------------------------------------------------------
__global__ void prep_kernel(const float* __restrict__ param,
                            const int*   __restrict__ decision) {
    int n = blockIdx.x * blockDim.x + threadIdx.x;
    if (n >= NTILES * NSTROKE) return;
    int t = n / NSTROKE;
    int i = n - t * NSTROKE;

    int d[NSTROKE];
    #pragma unroll
    for (int j = 0; j < NSTROKE; j++) d[j] = decision[t * NSTROKE + j];
    if (i == 0) {
        int cnt = 0;
        #pragma unroll
        for (int j = 0; j < NSTROKE; j++) cnt += (d[j] != 0);
        g_cnt[t] = cnt;
    }
    if (d[i] == 0) return;
    int pos = 0;
    #pragma unroll
    for (int j = 0; j < NSTROKE; j++) pos += (j < i) && (d[j] != 0);

    const float* q = param + (size_t)n * 12;
    float p[8];
    #pragma unroll
    for (int k = 0; k < 8; k++)
        p[k] = __fdividef(1.0f, 1.0f + __expf(-q[k]));   // jax.nn.sigmoid

    float x0 = p[0], y0 = p[1];
    float W = 12.5f * fmaxf(p[2], 0.01f);       // 25 * (wd/2)
    float H = 12.5f * fmaxf(p[3], 0.01f);
    float th = p[4] * 3.14159265358979323846f;
    float st, ct;
    __sincosf(th, &st, &ct);

    float C  = 25.0f * ct, S = 25.0f * st;
    float U0 = -(x0 * C + y0 * S);
    float V0 =  (x0 * S - y0 * C);

    int o = t * NSTROKE + pos;
    g_sA[o] = make_float4(C, S, U0, V0);
    g_sB[o] = make_float4(W, H, 0.f, 0.f);
    g_sC[o] = make_float4(p[5], p[6], p[7], 0.f);
}

// ---------------------------------------------------------------------------
// Kernel 2: ONE WARP renders one 16x16 padded cell (8 px/lane; lane =
// (tx 0..15, tyh 0..1), rows tyh + 2k). Warp-synchronous staging into a
// per-warp smem slab (entries in REVERSED blend order = front-to-back).
// Front-to-back blend: acc += c*(a*T); T -= a*T; out = acc + canvas*T
// (canvas DRAM reads after the loop). Grid sized for exactly one wave.
// ---------------------------------------------------------------------------
__global__ void __launch_bounds__(256, 4)
render_kernel(const float* __restrict__ canvas,
              float*       __restrict__ out) {
    __shared__ float4 slab[8][3 * 4 * NSTROKE];   // per warp: A[20],B[20],C[20]

    const int lane = threadIdx.x & 31;
    const int wrp  = threadIdx.x >> 5;
    const int cell = blockIdx.x * 8 + wrp;
    if (cell >= TOTCELL) return;

    const int a = cell / NCELL;          // padded cell row
    const int b = cell - a * NCELL;      // padded cell col

    float4* sA = &slab[wrp][0];
    float4* sB = &slab[wrp][4 * NSTROKE];
    float4* sC = &slab[wrp][8 * NSTROKE];

    // --- warp-synchronous staging ---
    const int PR[4] = {0, 1, 1, 0};
    const int PC[4] = {0, 1, 0, 1};
    int cntv = 0;
    if (lane < 4) {
        int p = lane;
        int r = (((a - 1) & 1) == PR[p]) ? (a - 1) : a;
        int c = (((b - 1) & 1) == PC[p]) ? (b - 1) : b;
        if ((unsigned)r < 64u && (unsigned)c < 64u)
            cntv = g_cnt[r * GRID_T + c];
    }
    const int cnt0 = __shfl_sync(0xffffffffu, cntv, 0);
    const int cnt1 = __shfl_sync(0xffffffffu, cntv, 1);
    const int cnt2 = __shfl_sync(0xffffffffu, cntv, 2);
    const int cnt3 = __shfl_sync(0xffffffffu, cntv, 3);
    const int tot  = cnt0 + cnt1 + cnt2 + cnt3;

    if (lane < 4 * NSTROKE) {
        int p = lane / NSTROKE, i = lane - p * NSTROKE;
        int cp   = (p == 0) ? cnt0 : (p == 1) ? cnt1 : (p == 2) ? cnt2 : cnt3;
        if (i < cp) {
            int base = ((p > 0) ? cnt0 : 0) + ((p > 1) ? cnt1 : 0) + ((p > 2) ? cnt2 : 0);
            int r = (((a - 1) & 1) == PR[p]) ? (a - 1) : a;
            int c = (((b - 1) & 1) == PC[p]) ? (b - 1) : b;
            int o = (r * GRID_T + c) * NSTROKE + i;
            float4 A = g_sA[o];
            float ox = ((float)(16 * (b - c)) + 0.5f) * 0.03125f;
            float oy = ((float)(16 * (a - r)) + 0.5f) * 0.03125f;
            float U0p = fmaf(ox, A.x, fmaf(oy, A.y, A.z));
            float V0p = fmaf(oy, A.x, fmaf(-ox, A.y, A.w));
            int e = tot - 1 - (base + i);        // reversed => front-to-back
            sA[e] = make_float4(A.x, A.y, U0p, V0p);
            sB[e] = g_sB[o];
            sC[e] = g_sC[o];
        }
    }
    __syncwarp();

    // --- 8 pixels per lane: x = 16b-8+tx, rows y = 16a-8 + tyh + 2k ---
    const int tx  = lane & 15;
    const int tyh = lane >> 4;           // 0..1
    const float gx  = (float)tx * 0.03125f;
    const float gy0 = (float)tyh * 0.03125f;

    float aR[8], aG[8], aB[8], T[8];
    #pragma unroll
    for (int k = 0; k < 8; k++) { aR[k] = aG[k] = aB[k] = 0.f; T[k] = 1.f; }

    for (int e = 0; e < tot; e++) {            // front-to-back
        float4 A  = sA[e];
        float4 B  = sB[e];
        float4 Cc = sC[e];

        float ub = fmaf(gx, A.x, A.z);         // u/v bases (gy term added per px)
        float vb = fmaf(-gx, A.y, A.w);

        #pragma unroll
        for (int k = 0; k < 8; k++) {
            float gyk = gy0 + (float)(2 * k) * 0.03125f;   // rows 2 apart
            float u = fmaf(gyk, A.y, ub);
            float v = fmaf(gyk, A.x, vb);
            float t1 = tanh_(B.x - fabsf(u));
            float t2 = tanh_(B.y - fabsf(v));
            float h1 = fmaf(t1, 0.5f, 0.5f);
            float h2 = fmaf(t2, 0.5f, 0.5f);
            float aT = h1 * h2 * T[k];          // alpha * transmittance
            aR[k] = fmaf(aT, Cc.x, aR[k]);
            aG[k] = fmaf(aT, Cc.y, aG[k]);
            aB[k] = fmaf(aT, Cc.z, aB[k]);
            T[k] -= aT;
        }
    }

    // --- late canvas read + composite ---
    const int x = 16 * b + tx - 8;       // q = 8
    if ((unsigned)x < (unsigned)IMG) {
        #pragma unroll
        for (int k = 0; k < 8; k++) {
            int y = 16 * a + tyh + 2 * k - 8;
            if ((unsigned)y < (unsigned)IMG) {
                int idx = y * IMG + x;
                out[idx]             = fmaf(canvas[idx],             T[k], aR[k]);
                out[PLANE + idx]     = fmaf(canvas[PLANE + idx],     T[k], aG[k]);
                out[2 * PLANE + idx] = fmaf(canvas[2 * PLANE + idx], T[k], aB[k]);
            }
        }
    }
}

// ---------------------------------------------------------------------------
extern "C" void kernel_launch(void* const* d_in, const int* in_sizes, int n_in,
                              void* d_out, int out_size) {
    const float* param    = (const float*)d_in[0];   // (1,64,64,5,12) f32
    const int*   decision = (const int*)  d_in[1];   // (1,64,64,5)    i32
    const float* canvas   = (const float*)d_in[2];   // (1,3,1024,1024) f32
    float*       out      = (float*)d_out;           // (1,3,1024,1024) f32

    prep_kernel<<<(NTILES * NSTROKE + 255) / 256, 256>>>(param, decision);

    // warp-per-cell: 4225 cells, 8 warps/block -> 529 blocks (one wave)
    render_kernel<<<(TOTCELL + 7) / 8, 256>>>(canvas, out);
}

// round 10
// speedup vs baseline: 1.0455x; 1.0455x over previous
#include <cuda_runtime.h>
#include <cuda_bf16.h>

// Problem constants: b=1, h=w=64, s=5, H=W=1024, ps=32, q=8
#define GRID_T   64
#define NTILES   (GRID_T * GRID_T)      // 4096
#define NSTROKE  5
#define IMG      1024
#define PLANE    (IMG * IMG)            // 1048576

__device__ __forceinline__ float tanh_(float x) {
    float r; asm("tanh.approx.f32 %0,%1;" : "=f"(r) : "f"(x)); return r;
}

// ---------------------------------------------------------------------------
// Single fused kernel. Block = one 16x16 padded-aligned cell, 64 threads
// (16x4), 4 pixels/thread (rows ty+{0,4,8,12}).
//
// Staging (threads 0..19, one per (pass, stroke)) does the whole prep inline:
// reads decision + raw params, computes sigmoid/sincos constants, folds the
// per-pass tile offset into U0/V0, and writes entries to smem in REVERSED
// blend order (=> front-to-back compositing). No prep kernel, no globals.
//
// Render: front-to-back transmittance blend; canvas is read AFTER the loop.
//   acc += color*(alpha*T);  T -= alpha*T;  out = acc + canvas*T
// ---------------------------------------------------------------------------
__global__ void __launch_bounds__(64)
render_kernel(const float* __restrict__ param,
              const int*   __restrict__ decision,
              const float* __restrict__ canvas,
              float*       __restrict__ out) {
    __shared__ float4 sA[4 * NSTROKE];   // (C, S, U0', V0')  [scaled by 25]
    __shared__ float4 sB[4 * NSTROKE];   // (W, H, dS, dC)    [scaled by 25]
    __shared__ float4 sC[4 * NSTROKE];   // (cr, cg, cb, -)
    __shared__ int    sCnt[4];

    const int a = blockIdx.y;            // padded cell row: Y in [16a, 16a+16)
    const int b = blockIdx.x;
    const int tx  = threadIdx.x;         // 0..15
    const int ty  = threadIdx.y;         // 0..3
    const int tid = ty * 16 + tx;

    // --- staging thread's (pass, stroke) assignment and tile ---
    const int PR[4] = {0, 1, 1, 0};
    const int PC[4] = {0, 1, 0, 1};
    int p = 0, i = 0, r = 0, c = 0, t = 0;
    bool valid = false;
    if (tid < 4 * NSTROKE) {
        p = tid / NSTROKE; i = tid - p * NSTROKE;
        r = (((a - 1) & 1) == PR[p]) ? (a - 1) : a;
        c = (((b - 1) & 1) == PC[p]) ? (b - 1) : b;
        valid = ((unsigned)r < 64u) && ((unsigned)c < 64u);
        t = r * GRID_T + c;
    }

    // --- phase 1: per-pass kept-stroke counts (threads i==0) ---
    int dec[NSTROKE];
    if (tid < 4 * NSTROKE && valid) {
        #pragma unroll
        for (int j = 0; j < NSTROKE; j++) dec[j] = decision[t * NSTROKE + j];
    } else {
        #pragma unroll
        for (int j = 0; j < NSTROKE; j++) dec[j] = 0;
    }
    if (tid < 4 * NSTROKE && i == 0) {
        int cnt = 0;
        #pragma unroll
        for (int j = 0; j < NSTROKE; j++) cnt += (dec[j] != 0);
        sCnt[p] = cnt;
    }
    __syncthreads();

    const int cnt0 = sCnt[0], cnt1 = sCnt[1], cnt2 = sCnt[2], cnt3 = sCnt[3];
    const int tot  = cnt0 + cnt1 + cnt2 + cnt3;

    // --- phase 2: inline prep + write entry (reversed position) ---
    if (tid < 4 * NSTROKE && dec[i] != 0) {
        int pos = 0;
        #pragma unroll
        for (int j = 0; j < NSTROKE; j++) pos += (j < i) && (dec[j] != 0);
        int base = ((p > 0) ? cnt0 : 0) + ((p > 1) ? cnt1 : 0) + ((p > 2) ? cnt2 : 0);
        int e = tot - 1 - (base + pos);          // reversed => front-to-back

        const float* q = param + (size_t)(t * NSTROKE + i) * 12;
        float p8[8];
        #pragma unroll
        for (int k = 0; k < 8; k++)
            p8[k] = __fdividef(1.0f, 1.0f + __expf(-q[k]));   // jax.nn.sigmoid

        float x0 = p8[0], y0 = p8[1];
        float W = 12.5f * fmaxf(p8[2], 0.01f);   // 25 * (wd/2)
        float H = 12.5f * fmaxf(p8[3], 0.01f);
        float th = p8[4] * 3.14159265358979323846f;
        float st, ct;
        __sincosf(th, &st, &ct);

        float C  = 25.0f * ct, S = 25.0f * st;
        float U0 = -(x0 * C + y0 * S);
        float V0 =  (x0 * S - y0 * C);

        // fold per-pass offset (cell-local coords start at tile offset ox,oy)
        float ox = ((float)(16 * (b - c)) + 0.5f) * 0.03125f;
        float oy = ((float)(16 * (a - r)) + 0.5f) * 0.03125f;
        float U0p = fmaf(ox, C, fmaf(oy, S, U0));
        float V0p = fmaf(oy, C, fmaf(-ox, S, V0));

        sA[e] = make_float4(C, S, U0p, V0p);
        sB[e] = make_float4(W, H, 0.125f * S, 0.125f * C);
        sC[e] = make_float4(p8[5], p8[6], p8[7], 0.f);
    }
    __syncthreads();

    // --- four pixels per thread: rows y0 + {0,4,8,12} ---
    const int x  = 16 * b + tx - 8;      // q = 8
    const int y0 = 16 * a + ty - 8;
    const bool vx = (unsigned)x < (unsigned)IMG;

    const float gx = (float)tx * 0.03125f;
    const float gy = (float)ty * 0.03125f;

    float aR[4] = {0.f, 0.f, 0.f, 0.f};
    float aG[4] = {0.f, 0.f, 0.f, 0.f};
    float aB[4] = {0.f, 0.f, 0.f, 0.f};
    float T[4]  = {1.f, 1.f, 1.f, 1.f};

    for (int e = 0; e < tot; e++) {            // front-to-back
        float4 A  = sA[e];
        float4 B  = sB[e];
        float4 Cc = sC[e];

        float u = fmaf(gx, A.x, fmaf(gy, A.y, A.z));
        float v = fmaf(gy, A.x, fmaf(-gx, A.y, A.w));

        #pragma unroll
        for (int k = 0; k < 4; k++) {
            float t1 = tanh_(B.x - fabsf(u));
            float t2 = tanh_(B.y - fabsf(v));
            float h1 = fmaf(t1, 0.5f, 0.5f);
            float h2 = fmaf(t2, 0.5f, 0.5f);
            float aT = h1 * h2 * T[k];          // alpha * transmittance
            aR[k] = fmaf(aT, Cc.x, aR[k]);
            aG[k] = fmaf(aT, Cc.y, aG[k]);
            aB[k] = fmaf(aT, Cc.z, aB[k]);
            T[k] -= aT;
            u += B.z;                           // +4 rows: du = 0.125*S
            v += B.w;                           //          dv = 0.125*C
        }
    }

    // --- late canvas read + composite ---
    #pragma unroll
    for (int k = 0; k < 4; k++) {
        int y = y0 + 4 * k;
        if (vx && ((unsigned)y < (unsigned)IMG)) {
            int idx = y * IMG + x;
            out[idx]             = fmaf(canvas[idx],             T[k], aR[k]);
            out[PLANE + idx]     = fmaf(canvas[PLANE + idx],     T[k], aG[k]);
            out[2 * PLANE + idx] = fmaf(canvas[2 * PLANE + idx], T[k], aB[k]);
        }
    }
}

// ---------------------------------------------------------------------------
extern "C" void kernel_launch(void* const* d_in, const int* in_sizes, int n_in,
                              void* d_out, int out_size) {
    const float* param    = (const float*)d_in[0];   // (1,64,64,5,12) f32
    const int*   decision = (const int*)  d_in[1];   // (1,64,64,5)    i32
    const float* canvas   = (const float*)d_in[2];   // (1,3,1024,1024) f32
    float*       out      = (float*)d_out;           // (1,3,1024,1024) f32

    dim3 bs(16, 4);          // 64 threads, 4 px/thread
    dim3 gs(65, 65);         // padded 1040x1040 in 16x16 cells
    render_kernel<<<gs, bs>>>(param, decision, canvas, out);
}